// round 16
// baseline (speedup 1.0000x reference)
#include <cuda_runtime.h>
#include <cuda_fp16.h>
#include <cstdint>

#define NN     50000
#define EE     625000
#define IN_EDGE 64
#define HH     128
#define HH2    256
#define OUTD   112
#define TILES_M 391   // ceil(50000/128)
#define NBM    782    // ceil(50000/64)
#define NB     196    // ceil(50000/256)

// ---------------- scratch (device globals; no allocation allowed) ----------
__device__ __align__(16) float g_seg[NN * IN_EDGE];
__device__ float g_inv[NN];
__device__ int   g_degi[NN];
__device__ int   g_rowptr[NN + 1];
__device__ int   g_cursor[NN];
__device__ int   g_bflag[NB];
__device__ int   g_csrc[EE];

// activations (x state double-buffered for fused gather+MLP)
__device__ __align__(16) __half g_xinh[NN * HH];
__device__ __align__(16) __half g_segh[NN * IN_EDGE];
__device__ __align__(16) __half g_x0h [NN * HH];
__device__ __align__(16) __half g_x0l [NN * HH];
__device__ __align__(16) __half g_x1h [NN * HH];
__device__ __align__(16) __half g_x1l [NN * HH];
__device__ __align__(16) __half g_eamh[NN * HH];
__device__ __align__(16) __half g_eaml[NN * HH];

// pre-rounded transposed weights, layout [N][K] fp16
__device__ __align__(16) __half g_whi[235520];

// ---------------------------------------------------------------------------
__device__ __forceinline__ uint32_t smem_u32(const void* p) {
    uint32_t a;
    asm("{ .reg .u64 t; cvta.to.shared.u64 t, %1; cvt.u32.u64 %0, t; }"
        : "=r"(a) : "l"(p));
    return a;
}
__device__ __forceinline__ void cp16(uint32_t dst, const void* src) {
    asm volatile("cp.async.cg.shared.global [%0], [%1], 16;"
                 :: "r"(dst), "l"(src) : "memory");
}
__device__ __forceinline__ void zero16(uint32_t dst) {
    asm volatile("st.shared.v4.b32 [%0], {%1,%1,%1,%1};" :: "r"(dst), "r"(0) : "memory");
}
__device__ __forceinline__ void ldsm4(uint32_t* r, uint32_t addr) {
    asm volatile("ldmatrix.sync.aligned.m8n8.x4.shared.b16 {%0,%1,%2,%3}, [%4];"
                 : "=r"(r[0]), "=r"(r[1]), "=r"(r[2]), "=r"(r[3]) : "r"(addr));
}
__device__ __forceinline__ void mma16816(float* d, const uint32_t* a, const uint32_t* b) {
    asm volatile("mma.sync.aligned.m16n8k16.row.col.f32.f16.f16.f32 "
                 "{%0,%1,%2,%3}, {%4,%5,%6,%7}, {%8,%9}, {%0,%1,%2,%3};"
                 : "+f"(d[0]), "+f"(d[1]), "+f"(d[2]), "+f"(d[3])
                 : "r"(a[0]), "r"(a[1]), "r"(a[2]), "r"(a[3]), "r"(b[0]), "r"(b[1]));
}
__device__ __forceinline__ void split2(float a, float b, uint32_t& hi, uint32_t& lo) {
    __half ha = __float2half(a), hb = __float2half(b);
    __half2 h = __halves2half2(ha, hb);
    __half2 l = __halves2half2(
        __float2half(a - __half2float(ha)),
        __float2half(b - __half2float(hb)));
    hi = *(uint32_t*)&h; lo = *(uint32_t*)&l;
}
__device__ __forceinline__ uint32_t pack2(float a, float b) {
    __half2 h = __halves2half2(__float2half(a), __float2half(b));
    return *(uint32_t*)&h;
}
__device__ __forceinline__ float2 unpack2(uint32_t h, uint32_t l) {
    __half2 hh = *(__half2*)&h;
    __half2 ll = *(__half2*)&l;
    return make_float2(__low2float(hh) + __low2float(ll),
                       __high2float(hh) + __high2float(ll));
}
__device__ __forceinline__ void red_add_v4(float* addr, float4 v) {
    asm volatile("red.global.add.v4.f32 [%0], {%1,%2,%3,%4};"
                 :: "l"(addr), "f"(v.x), "f"(v.y), "f"(v.z), "f"(v.w) : "memory");
}

// ---------------------------------------------------------------------------
// front: weight prep + degree histogram + seg scatter + x_in fp16 rounding
// ---------------------------------------------------------------------------
#define FB_W   920
#define FB_DEG 2442
#define FB_SEG 39063
#define FB_X   3125
__global__ void front_kernel(const float* __restrict__ node_W, const float* __restrict__ edge_W,
                             const float* __restrict__ W1, const float* __restrict__ W2,
                             const float* __restrict__ lin_W,
                             __half* __restrict__ hi,
                             const int* __restrict__ ei, int* __restrict__ degi,
                             const float* __restrict__ ea, float* __restrict__ seg,
                             const float* __restrict__ x_in, __half* __restrict__ xinh) {
    if (blockIdx.x < FB_W) {
        int i = blockIdx.x * 256 + threadIdx.x;
        if (i >= 235520) return;
        const float* src; int K, Nc, idx;
        if (i < 16384)       { src = node_W;                 K = 128; Nc = 128; idx = i; }
        else if (i < 24576)  { src = edge_W;                 K =  64; Nc = 128; idx = i - 16384; }
        else if (i < 122880) { int j = i - 24576;  src = W1 + (j / 32768) * 32768; K = 128; Nc = 256; idx = j % 32768; }
        else if (i < 221184) { int j = i - 122880; src = W2 + (j / 32768) * 32768; K = 256; Nc = 128; idx = j % 32768; }
        else                 { src = lin_W;                  K = 128; Nc = 112; idx = i - 221184; }
        int n = idx / K, k = idx % K;
        hi[i] = __float2half(__ldg(&src[(size_t)k * Nc + n]));
    } else if (blockIdx.x < FB_W + FB_DEG) {
        int e = (blockIdx.x - FB_W) * 256 + threadIdx.x;
        if (e < EE) atomicAdd(&degi[ei[EE + e]], 1);
    } else if (blockIdx.x < FB_W + FB_DEG + FB_SEG) {
        int gid = (blockIdx.x - FB_W - FB_DEG) * 256 + threadIdx.x;
        if (gid >= EE * 16) return;
        int e = gid >> 4, g = gid & 15;
        int dst = __ldg(&ei[EE + e]);
        float4 v = __ldg(((const float4*)ea) + (size_t)e * 16 + g);
        red_add_v4(seg + (size_t)dst * IN_EDGE + g * 4, v);
    } else {
        int gid = (blockIdx.x - FB_W - FB_DEG - FB_SEG) * 256 + threadIdx.x;
        size_t base = (size_t)gid * 8;
        if (base >= (size_t)NN * HH) return;
        float4 v0 = __ldg((const float4*)(x_in + base));
        float4 v1 = __ldg((const float4*)(x_in + base + 4));
        uint4 o;
        o.x = pack2(v0.x, v0.y); o.y = pack2(v0.z, v0.w);
        o.z = pack2(v1.x, v1.y); o.w = pack2(v1.z, v1.w);
        *(uint4*)(xinh + base) = o;
    }
}

// ---------------------------------------------------------------------------
// single-kernel exclusive scan (decoupled lookback over 196 blocks)
// ---------------------------------------------------------------------------
__global__ void scan_fused(const int* __restrict__ d, int* __restrict__ bflag,
                           int* __restrict__ rowptr, int* __restrict__ cursor,
                           float* __restrict__ inv) {
    __shared__ int s[256];
    __shared__ int sred[256];
    int b = blockIdx.x;
    int t = threadIdx.x;
    int i = b * 256 + t;
    int v = (i < NN) ? d[i] : 0;
    s[t] = v;
    __syncthreads();
    #pragma unroll
    for (int o = 1; o < 256; o <<= 1) {
        int tv = (t >= o) ? s[t - o] : 0;
        __syncthreads();
        s[t] += tv;
        __syncthreads();
    }
    int incl = s[t];
    int agg = s[255];
    if (t == 0) atomicExch(&bflag[b], agg + 1);
    int pval = 0;
    if (t < b) {
        int x;
        do { x = atomicAdd(&bflag[t], 0); } while (x == 0);
        pval = x - 1;
    }
    sred[t] = pval;
    __syncthreads();
    #pragma unroll
    for (int o = 128; o > 0; o >>= 1) {
        if (t < o) sred[t] += sred[t + o];
        __syncthreads();
    }
    int boffv = sred[0];
    if (i < NN) {
        int excl = incl - v + boffv;
        rowptr[i] = excl;
        cursor[i] = excl;
        inv[i] = 1.0f / (float)max(v, 1);
    }
    if (b == NB - 1 && t == 255) rowptr[NN] = boffv + agg;
}

// merged: seg fp32->fp16 conversion + csr fill
#define MB_SEG 1563
__global__ void mid_kernel(const float* __restrict__ seg, __half* __restrict__ segh,
                           const int* __restrict__ ei, int* __restrict__ cursor,
                           int* __restrict__ csrc) {
    if (blockIdx.x < MB_SEG) {
        size_t base = ((size_t)blockIdx.x * 256 + threadIdx.x) * 8;
        if (base >= (size_t)NN * IN_EDGE) return;
        float4 v0 = __ldg((const float4*)(seg + base));
        float4 v1 = __ldg((const float4*)(seg + base + 4));
        uint4 o;
        o.x = pack2(v0.x, v0.y); o.y = pack2(v0.z, v0.w);
        o.z = pack2(v1.x, v1.y); o.w = pack2(v1.z, v1.w);
        *(uint4*)(segh + base) = o;
    } else {
        int e = (blockIdx.x - MB_SEG) * 256 + threadIdx.x;
        if (e >= EE) return;
        int dst = __ldg(&ei[EE + e]);
        int p = atomicAdd(&cursor[dst], 1);
        csrc[p] = __ldg(&ei[e]);
    }
}

// ---------------------------------------------------------------------------
// Fused gather+combine+MLP (+head). Per 64-row CTA:
//  prologue: warps gather neighbor sums from Xin (global) and write the
//  combined tile straight into sC (smem) while W1 slab0 prefetches.
//  HEAD=1: phase 3 computes out = (xh+xl) @ lin_W + lin_b, x never global.
// ---------------------------------------------------------------------------
template <int HEAD>
__global__ void __launch_bounds__(128, HEAD ? 2 : 3)
mlp_fused(const int* __restrict__ rowptr, const int* __restrict__ csrc,
          const __half* __restrict__ Xin_h, const __half* __restrict__ Xin_l,
          const __half* __restrict__ eamh, const __half* __restrict__ eaml,
          const float* __restrict__ inv, const float* __restrict__ eps_p, int layer,
          const __half* __restrict__ W1h, const float* __restrict__ b1,
          const __half* __restrict__ W2h, const float* __restrict__ b2,
          __half* __restrict__ Xout_h, __half* __restrict__ Xout_l,
          const __half* __restrict__ Wlin, const float* __restrict__ blin,
          float* __restrict__ out) {
    extern __shared__ char smem[];
    const uint32_t sC = smem_u32(smem);
    const uint32_t sH = sC + 16384;
    const uint32_t sB = sC + 49152;
    const uint32_t sXh = sB + 16384;
    const uint32_t sXl = sXh + 16384;

    const int tid  = threadIdx.x;
    const int lane = tid & 31;
    const int wid  = tid >> 5;
    const int wm   = wid & 1;
    const int wn   = wid >> 1;
    const int rowBase = blockIdx.x * 64;

    const uint32_t aRowIdx = (uint32_t)(lane & 15);
    const uint32_t aK16    = (uint32_t)((lane >> 4) << 4);
    const uint32_t bRowIdx = (uint32_t)((lane & 7) + ((lane >> 4) << 3));
    const uint32_t bK16    = (uint32_t)(((lane >> 3) & 1) << 4);
    const int group = lane >> 2;
    const int qc    = (lane & 3) * 2;

    float acc[2][4][4];

    auto loadB = [&](const __half* W, int KT, int gn0, int kb, int stage, int NcB) {
        #pragma unroll
        for (int i = 0; i < 4; i++) {
            int f = tid + i * 128;
            int row = f >> 3, chn = f & 7;
            uint32_t addr = sB + stage * 8192 + row * 128 +
                            (((uint32_t)(chn * 16)) ^ ((row & 7) << 4));
            if (gn0 + row < NcB) cp16(addr, W + (size_t)(gn0 + row) * KT + kb + chn * 8);
            else                 zero16(addr);
        }
        asm volatile("cp.async.commit_group;" ::: "memory");
    };
    auto zacc = [&]() {
        #pragma unroll
        for (int a = 0; a < 2; a++)
            #pragma unroll
            for (int b = 0; b < 4; b++)
                #pragma unroll
                for (int c = 0; c < 4; c++) acc[a][b][c] = 0.f;
    };

    // prefetch W1 slab 0 so it overlaps the gather below
    loadB(W1h, 128, 0, 0, 0, 256);

    // ---------- fused gather + combine into sC (warp-per-node, 16 nodes/warp) ----
    {
        float epsv = 1.f + __ldg(&eps_p[layer]);
        for (int k = 0; k < 16; k++) {
            int rloc = wid * 16 + k;
            int w = rowBase + rloc;
            float v0 = 0.f, v1 = 0.f, v2 = 0.f, v3 = 0.f;
            if (w < NN) {
                int beg = __ldg(&rowptr[w]), end = __ldg(&rowptr[w + 1]);
                float a0 = 0.f, a1 = 0.f, a2 = 0.f, a3 = 0.f;
                for (int j = beg; j < end; j++) {
                    int s = __ldg(&csrc[j]);
                    uint2 hv = __ldg((const uint2*)(Xin_h + (size_t)s * HH) + lane);
                    __half2 h0 = *(__half2*)&hv.x;
                    __half2 h1 = *(__half2*)&hv.y;
                    a0 += __low2float(h0); a1 += __high2float(h0);
                    a2 += __low2float(h1); a3 += __high2float(h1);
                }
                float iv = __ldg(&inv[w]);
                uint2 hs = __ldg((const uint2*)(Xin_h + (size_t)w * HH) + lane);
                uint2 ls = __ldg((const uint2*)(Xin_l + (size_t)w * HH) + lane);
                float2 x01 = unpack2(hs.x, ls.x);
                float2 x23 = unpack2(hs.y, ls.y);
                uint2 eh = __ldg((const uint2*)(eamh + (size_t)w * HH) + lane);
                uint2 el = __ldg((const uint2*)(eaml + (size_t)w * HH) + lane);
                float2 e01 = unpack2(eh.x, el.x);
                float2 e23 = unpack2(eh.y, el.y);
                v0 = epsv * x01.x + a0 * iv + e01.x;
                v1 = epsv * x01.y + a1 * iv + e01.y;
                v2 = epsv * x23.x + a2 * iv + e23.x;
                v3 = epsv * x23.y + a3 * iv + e23.y;
            }
            uint32_t p0 = pack2(v0, v1), p1 = pack2(v2, v3);
            uint32_t addr = sC + rloc * 256 +
                            ((((uint32_t)(lane >> 1)) * 16) ^ ((uint32_t)(rloc & 7) << 4)) +
                            (lane & 1) * 8;
            asm volatile("st.shared.v2.b32 [%0], {%1,%2};"
                         :: "r"(addr), "r"(p0), "r"(p1) : "memory");
        }
    }
    __syncthreads();

    // ---------- phase 1: h1(smem) = relu(c @ W1 + b1), N=256, K=128 ----------
    for (int t = 0; t < 8; t++) {
        int cp = t >> 1, kc = t & 1;
        if (t + 1 < 8) {
            loadB(W1h, 128, ((t + 1) >> 1) * 64, ((t + 1) & 1) * 64, (t + 1) & 1, 256);
            asm volatile("cp.async.wait_group 1;" ::: "memory");
        } else {
            asm volatile("cp.async.wait_group 0;" ::: "memory");
        }
        __syncthreads();
        if (kc == 0) zacc();
        uint32_t bBuf = sB + (t & 1) * 8192;
        #pragma unroll
        for (int ks = 0; ks < 4; ks++) {
            uint32_t ah[2][4], bh[4][2];
            #pragma unroll
            for (int mi = 0; mi < 2; mi++) {
                uint32_t row = wm * 32 + mi * 16 + aRowIdx;
                uint32_t cb = (uint32_t)(kc * 128 + ks * 32) + aK16;
                ldsm4(ah[mi], sC + row * 256 + (cb ^ ((row & 7) << 4)));
            }
            #pragma unroll
            for (int pr = 0; pr < 2; pr++) {
                uint32_t row = wn * 32 + pr * 16 + bRowIdx;
                uint32_t cb = (uint32_t)(ks * 32) + bK16;
                uint32_t tr[4];
                ldsm4(tr, bBuf + row * 128 + (cb ^ ((row & 7) << 4)));
                bh[pr*2][0] = tr[0]; bh[pr*2][1] = tr[1];
                bh[pr*2+1][0] = tr[2]; bh[pr*2+1][1] = tr[3];
            }
            #pragma unroll
            for (int mi = 0; mi < 2; mi++)
                #pragma unroll
                for (int ni = 0; ni < 4; ni++)
                    mma16816(acc[mi][ni], ah[mi], bh[ni]);
        }
        if (kc == 1) {
            #pragma unroll
            for (int mi = 0; mi < 2; mi++) {
                int r0 = wm * 32 + mi * 16 + group;
                int r1 = r0 + 8;
                #pragma unroll
                for (int ni = 0; ni < 4; ni++) {
                    int c = cp * 64 + wn * 32 + ni * 8 + qc;
                    float bv0 = __ldg(&b1[c]), bv1 = __ldg(&b1[c + 1]);
                    uint32_t p0 = pack2(fmaxf(acc[mi][ni][0] + bv0, 0.f),
                                        fmaxf(acc[mi][ni][1] + bv1, 0.f));
                    uint32_t p1 = pack2(fmaxf(acc[mi][ni][2] + bv0, 0.f),
                                        fmaxf(acc[mi][ni][3] + bv1, 0.f));
                    uint32_t cb = (uint32_t)(c * 2);
                    uint32_t a0 = sH + r0 * 512 + (cb ^ ((r0 & 7) << 4));
                    uint32_t a1 = sH + r1 * 512 + (cb ^ ((r1 & 7) << 4));
                    asm volatile("st.shared.b32 [%0], %1;" :: "r"(a0), "r"(p0) : "memory");
                    asm volatile("st.shared.b32 [%0], %1;" :: "r"(a1), "r"(p1) : "memory");
                }
            }
        }
        __syncthreads();
    }

    // ---------- phase 2: x = relu(h1 @ W2 + b2), N=128, K=256 ----------
    loadB(W2h, 256, 0, 0, 0, 128);
    for (int t = 0; t < 8; t++) {
        int cp = t >> 2, kc = t & 3;
        if (t + 1 < 8) {
            loadB(W2h, 256, ((t + 1) >> 2) * 64, ((t + 1) & 3) * 64, (t + 1) & 1, 128);
            asm volatile("cp.async.wait_group 1;" ::: "memory");
        } else {
            asm volatile("cp.async.wait_group 0;" ::: "memory");
        }
        __syncthreads();
        if (kc == 0) zacc();
        uint32_t bBuf = sB + (t & 1) * 8192;
        #pragma unroll
        for (int ks = 0; ks < 4; ks++) {
            uint32_t ah[2][4], bh[4][2];
            #pragma unroll
            for (int mi = 0; mi < 2; mi++) {
                uint32_t row = wm * 32 + mi * 16 + aRowIdx;
                uint32_t cb = (uint32_t)(kc * 128 + ks * 32) + aK16;
                ldsm4(ah[mi], sH + row * 512 + (cb ^ ((row & 7) << 4)));
            }
            #pragma unroll
            for (int pr = 0; pr < 2; pr++) {
                uint32_t row = wn * 32 + pr * 16 + bRowIdx;
                uint32_t cb = (uint32_t)(ks * 32) + bK16;
                uint32_t tr[4];
                ldsm4(tr, bBuf + row * 128 + (cb ^ ((row & 7) << 4)));
                bh[pr*2][0] = tr[0]; bh[pr*2][1] = tr[1];
                bh[pr*2+1][0] = tr[2]; bh[pr*2+1][1] = tr[3];
            }
            #pragma unroll
            for (int mi = 0; mi < 2; mi++)
                #pragma unroll
                for (int ni = 0; ni < 4; ni++)
                    mma16816(acc[mi][ni], ah[mi], bh[ni]);
        }
        if (kc == 3) {
            #pragma unroll
            for (int mi = 0; mi < 2; mi++) {
                int rl0 = wm * 32 + mi * 16 + group;
                int rl1 = rl0 + 8;
                int r0 = rowBase + rl0;
                int r1 = rowBase + rl1;
                #pragma unroll
                for (int ni = 0; ni < 4; ni++) {
                    int c = cp * 64 + wn * 32 + ni * 8 + qc;
                    float bv0 = __ldg(&b2[c]), bv1 = __ldg(&b2[c + 1]);
                    float v00 = fmaxf(acc[mi][ni][0] + bv0, 0.f);
                    float v01 = fmaxf(acc[mi][ni][1] + bv1, 0.f);
                    float v10 = fmaxf(acc[mi][ni][2] + bv0, 0.f);
                    float v11 = fmaxf(acc[mi][ni][3] + bv1, 0.f);
                    uint32_t h0, l0, h1, l1;
                    split2(v00, v01, h0, l0);
                    split2(v10, v11, h1, l1);
                    if (HEAD == 0) {
                        if (r0 < NN) {
                            *(uint32_t*)(Xout_h + (size_t)r0 * HH + c) = h0;
                            *(uint32_t*)(Xout_l + (size_t)r0 * HH + c) = l0;
                        }
                        if (r1 < NN) {
                            *(uint32_t*)(Xout_h + (size_t)r1 * HH + c) = h1;
                            *(uint32_t*)(Xout_l + (size_t)r1 * HH + c) = l1;
                        }
                    } else {
                        uint32_t cb = (uint32_t)(c * 2);
                        uint32_t a0 = rl0 * 256 + (cb ^ ((rl0 & 7) << 4));
                        uint32_t a1 = rl1 * 256 + (cb ^ ((rl1 & 7) << 4));
                        asm volatile("st.shared.b32 [%0], %1;" :: "r"(sXh + a0), "r"(h0) : "memory");
                        asm volatile("st.shared.b32 [%0], %1;" :: "r"(sXl + a0), "r"(l0) : "memory");
                        asm volatile("st.shared.b32 [%0], %1;" :: "r"(sXh + a1), "r"(h1) : "memory");
                        asm volatile("st.shared.b32 [%0], %1;" :: "r"(sXl + a1), "r"(l1) : "memory");
                    }
                }
            }
        }
        __syncthreads();
    }

    // ---------- phase 3 (HEAD): out = (xh+xl) @ lin_W + lin_b ----------
    if (HEAD == 1) {
        loadB(Wlin, 128, 0, 0, 0, OUTD);
        for (int t = 0; t < 4; t++) {
            int cp = t >> 1, kc = t & 1;
            if (t + 1 < 4) {
                loadB(Wlin, 128, ((t + 1) >> 1) * 64, ((t + 1) & 1) * 64, (t + 1) & 1, OUTD);
                asm volatile("cp.async.wait_group 1;" ::: "memory");
            } else {
                asm volatile("cp.async.wait_group 0;" ::: "memory");
            }
            __syncthreads();
            if (kc == 0) zacc();
            uint32_t bBuf = sB + (t & 1) * 8192;
            #pragma unroll
            for (int ks = 0; ks < 4; ks++) {
                uint32_t ah[2][4], al[2][4], bh[4][2];
                #pragma unroll
                for (int mi = 0; mi < 2; mi++) {
                    uint32_t row = wm * 32 + mi * 16 + aRowIdx;
                    uint32_t cb = (uint32_t)(kc * 128 + ks * 32) + aK16;
                    uint32_t off = row * 256 + (cb ^ ((row & 7) << 4));
                    ldsm4(ah[mi], sXh + off);
                    ldsm4(al[mi], sXl + off);
                }
                #pragma unroll
                for (int pr = 0; pr < 2; pr++) {
                    uint32_t row = wn * 32 + pr * 16 + bRowIdx;
                    uint32_t cb = (uint32_t)(ks * 32) + bK16;
                    uint32_t tr[4];
                    ldsm4(tr, bBuf + row * 128 + (cb ^ ((row & 7) << 4)));
                    bh[pr*2][0] = tr[0]; bh[pr*2][1] = tr[1];
                    bh[pr*2+1][0] = tr[2]; bh[pr*2+1][1] = tr[3];
                }
                #pragma unroll
                for (int mi = 0; mi < 2; mi++)
                    #pragma unroll
                    for (int ni = 0; ni < 4; ni++) {
                        mma16816(acc[mi][ni], ah[mi], bh[ni]);
                        mma16816(acc[mi][ni], al[mi], bh[ni]);
                    }
            }
            if (kc == 1) {
                #pragma unroll
                for (int mi = 0; mi < 2; mi++) {
                    int r0 = rowBase + wm * 32 + mi * 16 + group;
                    int r1 = r0 + 8;
                    #pragma unroll
                    for (int ni = 0; ni < 4; ni++) {
                        int c = cp * 64 + wn * 32 + ni * 8 + qc;
                        if (c >= OUTD) continue;
                        float bv0 = __ldg(&blin[c]), bv1 = __ldg(&blin[c + 1]);
                        if (r0 < NN) {
                            float2 v; v.x = acc[mi][ni][0] + bv0; v.y = acc[mi][ni][1] + bv1;
                            *(float2*)(out + (size_t)r0 * OUTD + c) = v;
                        }
                        if (r1 < NN) {
                            float2 v; v.x = acc[mi][ni][2] + bv0; v.y = acc[mi][ni][3] + bv1;
                            *(float2*)(out + (size_t)r1 * OUTD + c) = v;
                        }
                    }
                }
            }
            __syncthreads();
        }
    }
}

// ---------------------------------------------------------------------------
// MERGED encoder kernel: grid (TILES_M, 4), 3 CTAs/SM.
// ---------------------------------------------------------------------------
__global__ void __launch_bounds__(256, 3)
enc_kernel(const __half* __restrict__ xinh, const __half* __restrict__ segh,
           const __half* __restrict__ wall,
           const float* __restrict__ node_b, const float* __restrict__ edge_b,
           __half* __restrict__ xh, __half* __restrict__ xl,
           __half* __restrict__ eamh, __half* __restrict__ eaml,
           const float* __restrict__ inv, const int* __restrict__ degi) {
    constexpr int STG = 24576;
    extern __shared__ char smem[];
    const uint32_t sb = smem_u32(smem);

    const int task = blockIdx.y >> 1;
    const int colBase = (blockIdx.y & 1) * 64;
    const int KT      = task ? 64 : 128;
    const int CHUNKS  = task ? 1 : 2;
    const __half* Ah  = task ? segh : xinh;
    const __half* Bhi = task ? (wall + 16384) : wall;
    const float* bias = task ? edge_b : node_b;
    __half* Ch = task ? eamh : xh;
    __half* Cl = task ? eaml : xl;

    const int tid  = threadIdx.x;
    const int lane = tid & 31;
    const int wid  = tid >> 5;
    const int wm   = wid & 3;
    const int wn   = wid >> 2;
    const int rowBase = blockIdx.x * 128;

    float acc[2][4][4];
    #pragma unroll
    for (int a = 0; a < 2; a++)
        #pragma unroll
        for (int b = 0; b < 4; b++)
            #pragma unroll
            for (int c = 0; c < 4; c++) acc[a][b][c] = 0.f;

    auto load_slab = [&](int stage, int c) {
        uint32_t base = sb + stage * STG;
        int kb = c * 64;
        #pragma unroll
        for (int i = 0; i < 4; i++) {
            int f = tid + i * 256;
            int row = f >> 3, chn = f & 7;
            uint32_t sw = (uint32_t)(chn * 16) ^ (uint32_t)((row & 7) << 4);
            uint32_t da = base + row * 128 + sw;
            int gr = rowBase + row;
            if (gr < NN) cp16(da, Ah + (size_t)gr * KT + kb + chn * 8);
            else         zero16(da);
        }
        #pragma unroll
        for (int i = 0; i < 2; i++) {
            int f = tid + i * 256;
            int row = f >> 3, chn = f & 7;
            uint32_t sw = (uint32_t)(chn * 16) ^ (uint32_t)((row & 7) << 4);
            uint32_t db = base + 16384 + row * 128 + sw;
            cp16(db, Bhi + (size_t)(colBase + row) * KT + kb + chn * 8);
        }
        asm volatile("cp.async.commit_group;" ::: "memory");
    };

    const uint32_t aRowIdx = (uint32_t)(lane & 15);
    const uint32_t aK16    = (uint32_t)((lane >> 4) << 4);
    const uint32_t bRowIdx = (uint32_t)((lane & 7) + ((lane >> 4) << 3));
    const uint32_t bK16    = (uint32_t)(((lane >> 3) & 1) << 4);

    load_slab(0, 0);

    for (int c = 0; c < CHUNKS; c++) {
        if (c + 1 < CHUNKS) {
            load_slab((c + 1) & 1, c + 1);
            asm volatile("cp.async.wait_group 1;" ::: "memory");
        } else {
            asm volatile("cp.async.wait_group 0;" ::: "memory");
        }
        __syncthreads();

        uint32_t bA = sb + (c & 1) * STG;
        uint32_t bB = bA + 16384;
        #pragma unroll
        for (int ks = 0; ks < 4; ks++) {
            uint32_t ah[2][4], bh[4][2];
            #pragma unroll
            for (int mi = 0; mi < 2; mi++) {
                uint32_t row = wm * 32 + mi * 16 + aRowIdx;
                uint32_t cb = (uint32_t)(ks * 32) + aK16;
                ldsm4(ah[mi], bA + row * 128 + (cb ^ ((row & 7) << 4)));
            }
            #pragma unroll
            for (int pr = 0; pr < 2; pr++) {
                uint32_t row = wn * 32 + pr * 16 + bRowIdx;
                uint32_t cb = (uint32_t)(ks * 32) + bK16;
                uint32_t t[4];
                ldsm4(t, bB + row * 128 + (cb ^ ((row & 7) << 4)));
                bh[pr*2][0] = t[0]; bh[pr*2][1] = t[1];
                bh[pr*2+1][0] = t[2]; bh[pr*2+1][1] = t[3];
            }
            #pragma unroll
            for (int mi = 0; mi < 2; mi++)
                #pragma unroll
                for (int ni = 0; ni < 4; ni++)
                    mma16816(acc[mi][ni], ah[mi], bh[ni]);
        }
        if (c + 1 < CHUNKS) __syncthreads();
    }

    const int group = lane >> 2;
    const int qc    = (lane & 3) * 2;
    #pragma unroll
    for (int mi = 0; mi < 2; mi++) {
        int r0 = rowBase + wm * 32 + mi * 16 + group;
        int r1 = r0 + 8;
        float iv0 = 0.f, m0 = 0.f, iv1 = 0.f, m1 = 0.f;
        if (task == 1) {
            if (r0 < NN) { iv0 = __ldg(&inv[r0]); m0 = (__ldg(&degi[r0]) > 0) ? 1.f : 0.f; }
            if (r1 < NN) { iv1 = __ldg(&inv[r1]); m1 = (__ldg(&degi[r1]) > 0) ? 1.f : 0.f; }
        }
        #pragma unroll
        for (int ni = 0; ni < 4; ni++) {
            int c = colBase + wn * 32 + ni * 8 + qc;
            float b0 = __ldg(&bias[c]), b1 = __ldg(&bias[c + 1]);
            float2 v0, v1;
            if (task == 1) {
                v0.x = acc[mi][ni][0] * iv0 + m0 * b0;
                v0.y = acc[mi][ni][1] * iv0 + m0 * b1;
                v1.x = acc[mi][ni][2] * iv1 + m1 * b0;
                v1.y = acc[mi][ni][3] * iv1 + m1 * b1;
            } else {
                v0.x = acc[mi][ni][0] + b0; v0.y = acc[mi][ni][1] + b1;
                v1.x = acc[mi][ni][2] + b0; v1.y = acc[mi][ni][3] + b1;
            }
            if (r0 < NN) {
                uint32_t h, l; split2(v0.x, v0.y, h, l);
                *(uint32_t*)(Ch + (size_t)r0 * HH + c) = h;
                *(uint32_t*)(Cl + (size_t)r0 * HH + c) = l;
            }
            if (r1 < NN) {
                uint32_t h, l; split2(v1.x, v1.y, h, l);
                *(uint32_t*)(Ch + (size_t)r1 * HH + c) = h;
                *(uint32_t*)(Cl + (size_t)r1 * HH + c) = l;
            }
        }
    }
}

// ---------------------------------------------------------------------------
extern "C" void kernel_launch(void* const* d_in, const int* in_sizes, int n_in,
                              void* d_out, int out_size) {
    const float* x_in   = (const float*)d_in[0];
    const float* eattr  = (const float*)d_in[1];
    const int*   eidx   = (const int*)  d_in[2];
    const float* node_W = (const float*)d_in[3];
    const float* node_b = (const float*)d_in[4];
    const float* edge_W = (const float*)d_in[5];
    const float* edge_b = (const float*)d_in[6];
    const float* W1     = (const float*)d_in[7];
    const float* b1     = (const float*)d_in[8];
    const float* W2     = (const float*)d_in[9];
    const float* b2     = (const float*)d_in[10];
    const float* eps    = (const float*)d_in[11];
    const float* lin_W  = (const float*)d_in[12];
    const float* lin_b  = (const float*)d_in[13];
    float* out = (float*)d_out;

    float *pseg, *pinv;
    int *pdegi, *prowptr, *pcursor, *pbflag, *pcsrc;
    __half *pwh, *px0h, *px0l, *px1h, *px1l, *peamh, *peaml, *pxinh, *psegh;
    cudaGetSymbolAddress((void**)&pseg, g_seg);
    cudaGetSymbolAddress((void**)&pinv, g_inv);
    cudaGetSymbolAddress((void**)&pdegi, g_degi);
    cudaGetSymbolAddress((void**)&prowptr, g_rowptr);
    cudaGetSymbolAddress((void**)&pcursor, g_cursor);
    cudaGetSymbolAddress((void**)&pbflag, g_bflag);
    cudaGetSymbolAddress((void**)&pcsrc, g_csrc);
    cudaGetSymbolAddress((void**)&pwh,  g_whi);
    cudaGetSymbolAddress((void**)&px0h, g_x0h);
    cudaGetSymbolAddress((void**)&px0l, g_x0l);
    cudaGetSymbolAddress((void**)&px1h, g_x1h);
    cudaGetSymbolAddress((void**)&px1l, g_x1l);
    cudaGetSymbolAddress((void**)&peamh, g_eamh);
    cudaGetSymbolAddress((void**)&peaml, g_eaml);
    cudaGetSymbolAddress((void**)&pxinh, g_xinh);
    cudaGetSymbolAddress((void**)&psegh, g_segh);

    constexpr int SM_ENC  = 49152;
    constexpr int SM_MLP0 = 65536;
    constexpr int SM_MLP1 = 98304;
    auto setsm = [](const void* f, int b) {
        cudaFuncSetAttribute(f, cudaFuncAttributeMaxDynamicSharedMemorySize, b);
    };
    setsm((const void*)enc_kernel, SM_ENC);
    setsm((const void*)mlp_fused<0>, SM_MLP0);
    setsm((const void*)mlp_fused<1>, SM_MLP1);

    // ---- resets ----
    cudaMemsetAsync(pdegi, 0, NN * sizeof(int));
    cudaMemsetAsync(pseg, 0, (size_t)NN * IN_EDGE * sizeof(float));
    cudaMemsetAsync(pbflag, 0, NB * sizeof(int));

    // ---- front: weight prep + deg + seg scatter + x_in round ----
    front_kernel<<<FB_W + FB_DEG + FB_SEG + FB_X, 256>>>(
        node_W, edge_W, W1, W2, lin_W, pwh, eidx, pdegi, eattr, pseg, x_in, pxinh);

    // ---- scan, then merged seg2h + csr_fill ----
    scan_fused<<<NB, 256>>>(pdegi, pbflag, prowptr, pcursor, pinv);
    mid_kernel<<<MB_SEG + (EE + 255) / 256, 256>>>(pseg, psegh, eidx, pcursor, pcsrc);

    // ---- merged encoders (node + edge in one launch); x state -> buffer 0 ----
    enc_kernel<<<dim3(TILES_M, 4), 256, SM_ENC>>>(pxinh, psegh, pwh,
        node_b, edge_b, px0h, px0l, peamh, peaml, pinv, pdegi);

    // ---- layers: fused gather+MLP, double-buffered x state ----
    // l0: x0 -> x1 ; l1: x1 -> x0 ; l2(HEAD): x0 -> out
    mlp_fused<0><<<NBM, 128, SM_MLP0>>>(prowptr, pcsrc, px0h, px0l,
        peamh, peaml, pinv, eps, 0,
        pwh + 24576, b1, pwh + 122880, b2,
        px1h, px1l, nullptr, nullptr, nullptr);
    mlp_fused<0><<<NBM, 128, SM_MLP0>>>(prowptr, pcsrc, px1h, px1l,
        peamh, peaml, pinv, eps, 1,
        pwh + 24576 + 32768, b1 + HH2, pwh + 122880 + 32768, b2 + HH,
        px0h, px0l, nullptr, nullptr, nullptr);
    mlp_fused<1><<<NBM, 128, SM_MLP1>>>(prowptr, pcsrc, px0h, px0l,
        peamh, peaml, pinv, eps, 2,
        pwh + 24576 + 65536, b1 + 2 * HH2, pwh + 122880 + 65536, b2 + 2 * HH,
        nullptr, nullptr, pwh + 221184, lin_b, out);
}

// round 17
// speedup vs baseline: 1.5455x; 1.5455x over previous
#include <cuda_runtime.h>
#include <cuda_fp16.h>
#include <cstdint>

#define NN     50000
#define EE     625000
#define IN_EDGE 64
#define HH     128
#define HH2    256
#define OUTD   112
#define TILES_M 391   // ceil(50000/128)
#define NBM    782    // ceil(50000/64)
#define NB     196    // ceil(50000/256)

// ---------------- scratch (device globals; no allocation allowed) ----------
__device__ __align__(16) float g_seg[NN * IN_EDGE];
__device__ float g_inv[NN];
__device__ int   g_degi[NN];
__device__ int   g_rowptr[NN + 1];
__device__ int   g_cursor[NN];
__device__ int   g_bflag[NB];
__device__ int   g_csrc[EE];

// activations
__device__ __align__(16) __half g_xinh[NN * HH];     // x_in rounded fp16
__device__ __align__(16) __half g_segh[NN * IN_EDGE];// seg rounded fp16
__device__ __align__(16) __half g_ch  [NN * HH];     // combined (hi), W1 input
__device__ __align__(16) __half g_xh  [NN * HH];     // node state (split hi)
__device__ __align__(16) __half g_xl  [NN * HH];     // node state (split lo)
__device__ __align__(16) __half g_eamh[NN * HH];     // edge-agg-mean (split)
__device__ __align__(16) __half g_eaml[NN * HH];

// pre-rounded transposed weights, layout [N][K] fp16
__device__ __align__(16) __half g_whi[235520];

// ---------------------------------------------------------------------------
__device__ __forceinline__ uint32_t smem_u32(const void* p) {
    uint32_t a;
    asm("{ .reg .u64 t; cvta.to.shared.u64 t, %1; cvt.u32.u64 %0, t; }"
        : "=r"(a) : "l"(p));
    return a;
}
__device__ __forceinline__ void cp16(uint32_t dst, const void* src) {
    asm volatile("cp.async.cg.shared.global [%0], [%1], 16;"
                 :: "r"(dst), "l"(src) : "memory");
}
__device__ __forceinline__ void zero16(uint32_t dst) {
    asm volatile("st.shared.v4.b32 [%0], {%1,%1,%1,%1};" :: "r"(dst), "r"(0) : "memory");
}
__device__ __forceinline__ void ldsm4(uint32_t* r, uint32_t addr) {
    asm volatile("ldmatrix.sync.aligned.m8n8.x4.shared.b16 {%0,%1,%2,%3}, [%4];"
                 : "=r"(r[0]), "=r"(r[1]), "=r"(r[2]), "=r"(r[3]) : "r"(addr));
}
__device__ __forceinline__ void mma16816(float* d, const uint32_t* a, const uint32_t* b) {
    asm volatile("mma.sync.aligned.m16n8k16.row.col.f32.f16.f16.f32 "
                 "{%0,%1,%2,%3}, {%4,%5,%6,%7}, {%8,%9}, {%0,%1,%2,%3};"
                 : "+f"(d[0]), "+f"(d[1]), "+f"(d[2]), "+f"(d[3])
                 : "r"(a[0]), "r"(a[1]), "r"(a[2]), "r"(a[3]), "r"(b[0]), "r"(b[1]));
}
__device__ __forceinline__ void split2(float a, float b, uint32_t& hi, uint32_t& lo) {
    __half ha = __float2half(a), hb = __float2half(b);
    __half2 h = __halves2half2(ha, hb);
    __half2 l = __halves2half2(
        __float2half(a - __half2float(ha)),
        __float2half(b - __half2float(hb)));
    hi = *(uint32_t*)&h; lo = *(uint32_t*)&l;
}
__device__ __forceinline__ uint32_t pack2(float a, float b) {
    __half2 h = __halves2half2(__float2half(a), __float2half(b));
    return *(uint32_t*)&h;
}
__device__ __forceinline__ float2 unpack2(uint32_t h, uint32_t l) {
    __half2 hh = *(__half2*)&h;
    __half2 ll = *(__half2*)&l;
    return make_float2(__low2float(hh) + __low2float(ll),
                       __high2float(hh) + __high2float(ll));
}
__device__ __forceinline__ void red_add_v4(float* addr, float4 v) {
    asm volatile("red.global.add.v4.f32 [%0], {%1,%2,%3,%4};"
                 :: "l"(addr), "f"(v.x), "f"(v.y), "f"(v.z), "f"(v.w) : "memory");
}

// ---------------------------------------------------------------------------
// front: weight prep + degree histogram + seg scatter + x_in fp16 rounding
// ---------------------------------------------------------------------------
#define FB_W   920
#define FB_DEG 2442
#define FB_SEG 39063
#define FB_X   3125
__global__ void front_kernel(const float* __restrict__ node_W, const float* __restrict__ edge_W,
                             const float* __restrict__ W1, const float* __restrict__ W2,
                             const float* __restrict__ lin_W,
                             __half* __restrict__ hi,
                             const int* __restrict__ ei, int* __restrict__ degi,
                             const float* __restrict__ ea, float* __restrict__ seg,
                             const float* __restrict__ x_in, __half* __restrict__ xinh) {
    if (blockIdx.x < FB_W) {
        int i = blockIdx.x * 256 + threadIdx.x;
        if (i >= 235520) return;
        const float* src; int K, Nc, idx;
        if (i < 16384)       { src = node_W;                 K = 128; Nc = 128; idx = i; }
        else if (i < 24576)  { src = edge_W;                 K =  64; Nc = 128; idx = i - 16384; }
        else if (i < 122880) { int j = i - 24576;  src = W1 + (j / 32768) * 32768; K = 128; Nc = 256; idx = j % 32768; }
        else if (i < 221184) { int j = i - 122880; src = W2 + (j / 32768) * 32768; K = 256; Nc = 128; idx = j % 32768; }
        else                 { src = lin_W;                  K = 128; Nc = 112; idx = i - 221184; }
        int n = idx / K, k = idx % K;
        hi[i] = __float2half(__ldg(&src[(size_t)k * Nc + n]));
    } else if (blockIdx.x < FB_W + FB_DEG) {
        int e = (blockIdx.x - FB_W) * 256 + threadIdx.x;
        if (e < EE) atomicAdd(&degi[ei[EE + e]], 1);
    } else if (blockIdx.x < FB_W + FB_DEG + FB_SEG) {
        int gid = (blockIdx.x - FB_W - FB_DEG) * 256 + threadIdx.x;
        if (gid >= EE * 16) return;
        int e = gid >> 4, g = gid & 15;
        int dst = __ldg(&ei[EE + e]);
        float4 v = __ldg(((const float4*)ea) + (size_t)e * 16 + g);
        red_add_v4(seg + (size_t)dst * IN_EDGE + g * 4, v);
    } else {
        int gid = (blockIdx.x - FB_W - FB_DEG - FB_SEG) * 256 + threadIdx.x;
        size_t base = (size_t)gid * 8;
        if (base >= (size_t)NN * HH) return;
        float4 v0 = __ldg((const float4*)(x_in + base));
        float4 v1 = __ldg((const float4*)(x_in + base + 4));
        uint4 o;
        o.x = pack2(v0.x, v0.y); o.y = pack2(v0.z, v0.w);
        o.z = pack2(v1.x, v1.y); o.w = pack2(v1.z, v1.w);
        *(uint4*)(xinh + base) = o;
    }
}

// ---------------------------------------------------------------------------
// single-kernel exclusive scan (decoupled lookback over 196 blocks)
// ---------------------------------------------------------------------------
__global__ void scan_fused(const int* __restrict__ d, int* __restrict__ bflag,
                           int* __restrict__ rowptr, int* __restrict__ cursor,
                           float* __restrict__ inv) {
    __shared__ int s[256];
    __shared__ int sred[256];
    int b = blockIdx.x;
    int t = threadIdx.x;
    int i = b * 256 + t;
    int v = (i < NN) ? d[i] : 0;
    s[t] = v;
    __syncthreads();
    #pragma unroll
    for (int o = 1; o < 256; o <<= 1) {
        int tv = (t >= o) ? s[t - o] : 0;
        __syncthreads();
        s[t] += tv;
        __syncthreads();
    }
    int incl = s[t];
    int agg = s[255];
    if (t == 0) atomicExch(&bflag[b], agg + 1);
    int pval = 0;
    if (t < b) {
        int x;
        do { x = atomicAdd(&bflag[t], 0); } while (x == 0);
        pval = x - 1;
    }
    sred[t] = pval;
    __syncthreads();
    #pragma unroll
    for (int o = 128; o > 0; o >>= 1) {
        if (t < o) sred[t] += sred[t + o];
        __syncthreads();
    }
    int boffv = sred[0];
    if (i < NN) {
        int excl = incl - v + boffv;
        rowptr[i] = excl;
        cursor[i] = excl;
        inv[i] = 1.0f / (float)max(v, 1);
    }
    if (b == NB - 1 && t == 255) rowptr[NN] = boffv + agg;
}

// merged: seg fp32->fp16 conversion + csr fill
#define MB_SEG 1563
__global__ void mid_kernel(const float* __restrict__ seg, __half* __restrict__ segh,
                           const int* __restrict__ ei, int* __restrict__ cursor,
                           int* __restrict__ csrc) {
    if (blockIdx.x < MB_SEG) {
        size_t base = ((size_t)blockIdx.x * 256 + threadIdx.x) * 8;
        if (base >= (size_t)NN * IN_EDGE) return;
        float4 v0 = __ldg((const float4*)(seg + base));
        float4 v1 = __ldg((const float4*)(seg + base + 4));
        uint4 o;
        o.x = pack2(v0.x, v0.y); o.y = pack2(v0.z, v0.w);
        o.z = pack2(v1.x, v1.y); o.w = pack2(v1.z, v1.w);
        *(uint4*)(segh + base) = o;
    } else {
        int e = (blockIdx.x - MB_SEG) * 256 + threadIdx.x;
        if (e >= EE) return;
        int dst = __ldg(&ei[EE + e]);
        int p = atomicAdd(&cursor[dst], 1);
        csrc[p] = __ldg(&ei[e]);
    }
}

// fused: agg = sum_neighbors(x_hi) ; c = (1+eps)*x + agg*inv + eam -> ch (fp16 hi)
__global__ void gather_combine(const int* __restrict__ rowptr, const int* __restrict__ csrc,
                               const __half* __restrict__ xh,
                               const __half* __restrict__ xl,
                               const __half* __restrict__ eamh,
                               const __half* __restrict__ eaml,
                               const float* __restrict__ inv,
                               const float* __restrict__ eps_p, int layer,
                               __half* __restrict__ ch) {
    int w = (blockIdx.x * blockDim.x + threadIdx.x) >> 5;
    if (w >= NN) return;
    int lane = threadIdx.x & 31;
    int beg = __ldg(&rowptr[w]), end = __ldg(&rowptr[w + 1]);
    float a0 = 0.f, a1 = 0.f, a2 = 0.f, a3 = 0.f;
    for (int j = beg; j < end; j++) {
        int s = __ldg(&csrc[j]);
        uint2 hv = __ldg((const uint2*)(xh + (size_t)s * HH) + lane);
        __half2 h0 = *(__half2*)&hv.x;
        __half2 h1 = *(__half2*)&hv.y;
        a0 += __low2float(h0); a1 += __high2float(h0);
        a2 += __low2float(h1); a3 += __high2float(h1);
    }
    float iv = __ldg(&inv[w]);
    float epsv = 1.f + __ldg(&eps_p[layer]);
    uint2 hs = __ldg((const uint2*)(xh + (size_t)w * HH) + lane);
    uint2 ls = __ldg((const uint2*)(xl + (size_t)w * HH) + lane);
    float2 x01 = unpack2(hs.x, ls.x);
    float2 x23 = unpack2(hs.y, ls.y);
    uint2 eh = __ldg((const uint2*)(eamh + (size_t)w * HH) + lane);
    uint2 el = __ldg((const uint2*)(eaml + (size_t)w * HH) + lane);
    float2 e01 = unpack2(eh.x, el.x);
    float2 e23 = unpack2(eh.y, el.y);
    uint2 h;
    h.x = pack2(epsv * x01.x + a0 * iv + e01.x, epsv * x01.y + a1 * iv + e01.y);
    h.y = pack2(epsv * x23.x + a2 * iv + e23.x, epsv * x23.y + a3 * iv + e23.y);
    *(uint2*)(ch + (size_t)w * HH + lane * 4) = h;
}

// ---------------------------------------------------------------------------
// Fused GIN MLP (HEAD=1: + output head in phase 3, x never hits global).
// HEAD=0 runs 3 CTAs/SM (64KB smem); HEAD=1 runs 2 (96KB smem).
// ---------------------------------------------------------------------------
template <int HEAD>
__global__ void __launch_bounds__(128, HEAD ? 2 : 3)
mlp_fused(const __half* __restrict__ C, const __half* __restrict__ W1h,
          const float* __restrict__ b1, const __half* __restrict__ W2h,
          const float* __restrict__ b2,
          __half* __restrict__ Xh, __half* __restrict__ Xl,
          const __half* __restrict__ Wlin, const float* __restrict__ blin,
          float* __restrict__ out) {
    extern __shared__ char smem[];
    const uint32_t sC = smem_u32(smem);
    const uint32_t sH = sC + 16384;
    const uint32_t sB = sC + 49152;
    const uint32_t sXh = sB + 16384;
    const uint32_t sXl = sXh + 16384;

    const int tid  = threadIdx.x;
    const int lane = tid & 31;
    const int wid  = tid >> 5;
    const int wm   = wid & 1;
    const int wn   = wid >> 1;
    const int rowBase = blockIdx.x * 64;

    #pragma unroll
    for (int i = 0; i < 8; i++) {
        int f = tid + i * 128;
        int row = f >> 4, chn = f & 15;
        uint32_t addr = sC + row * 256 + (((uint32_t)(chn * 16)) ^ ((row & 7) << 4));
        int gr = rowBase + row;
        if (gr < NN) cp16(addr, C + (size_t)gr * HH + chn * 8);
        else         zero16(addr);
    }
    asm volatile("cp.async.commit_group;" ::: "memory");

    const uint32_t aRowIdx = (uint32_t)(lane & 15);
    const uint32_t aK16    = (uint32_t)((lane >> 4) << 4);
    const uint32_t bRowIdx = (uint32_t)((lane & 7) + ((lane >> 4) << 3));
    const uint32_t bK16    = (uint32_t)(((lane >> 3) & 1) << 4);
    const int group = lane >> 2;
    const int qc    = (lane & 3) * 2;

    float acc[2][4][4];

    auto loadB = [&](const __half* W, int KT, int gn0, int kb, int stage, int NcB) {
        #pragma unroll
        for (int i = 0; i < 4; i++) {
            int f = tid + i * 128;
            int row = f >> 3, chn = f & 7;
            uint32_t addr = sB + stage * 8192 + row * 128 +
                            (((uint32_t)(chn * 16)) ^ ((row & 7) << 4));
            if (gn0 + row < NcB) cp16(addr, W + (size_t)(gn0 + row) * KT + kb + chn * 8);
            else                 zero16(addr);
        }
        asm volatile("cp.async.commit_group;" ::: "memory");
    };
    auto zacc = [&]() {
        #pragma unroll
        for (int a = 0; a < 2; a++)
            #pragma unroll
            for (int b = 0; b < 4; b++)
                #pragma unroll
                for (int c = 0; c < 4; c++) acc[a][b][c] = 0.f;
    };

    // ---------- phase 1: h1(smem) = relu(c @ W1 + b1), N=256, K=128 ----------
    loadB(W1h, 128, 0, 0, 0, 256);
    for (int t = 0; t < 8; t++) {
        int cp = t >> 1, kc = t & 1;
        if (t + 1 < 8) {
            loadB(W1h, 128, ((t + 1) >> 1) * 64, ((t + 1) & 1) * 64, (t + 1) & 1, 256);
            asm volatile("cp.async.wait_group 1;" ::: "memory");
        } else {
            asm volatile("cp.async.wait_group 0;" ::: "memory");
        }
        __syncthreads();
        if (kc == 0) zacc();
        uint32_t bBuf = sB + (t & 1) * 8192;
        #pragma unroll
        for (int ks = 0; ks < 4; ks++) {
            uint32_t ah[2][4], bh[4][2];
            #pragma unroll
            for (int mi = 0; mi < 2; mi++) {
                uint32_t row = wm * 32 + mi * 16 + aRowIdx;
                uint32_t cb = (uint32_t)(kc * 128 + ks * 32) + aK16;
                ldsm4(ah[mi], sC + row * 256 + (cb ^ ((row & 7) << 4)));
            }
            #pragma unroll
            for (int pr = 0; pr < 2; pr++) {
                uint32_t row = wn * 32 + pr * 16 + bRowIdx;
                uint32_t cb = (uint32_t)(ks * 32) + bK16;
                uint32_t tr[4];
                ldsm4(tr, bBuf + row * 128 + (cb ^ ((row & 7) << 4)));
                bh[pr*2][0] = tr[0]; bh[pr*2][1] = tr[1];
                bh[pr*2+1][0] = tr[2]; bh[pr*2+1][1] = tr[3];
            }
            #pragma unroll
            for (int mi = 0; mi < 2; mi++)
                #pragma unroll
                for (int ni = 0; ni < 4; ni++)
                    mma16816(acc[mi][ni], ah[mi], bh[ni]);
        }
        if (kc == 1) {
            #pragma unroll
            for (int mi = 0; mi < 2; mi++) {
                int r0 = wm * 32 + mi * 16 + group;
                int r1 = r0 + 8;
                #pragma unroll
                for (int ni = 0; ni < 4; ni++) {
                    int c = cp * 64 + wn * 32 + ni * 8 + qc;
                    float bv0 = __ldg(&b1[c]), bv1 = __ldg(&b1[c + 1]);
                    uint32_t p0 = pack2(fmaxf(acc[mi][ni][0] + bv0, 0.f),
                                        fmaxf(acc[mi][ni][1] + bv1, 0.f));
                    uint32_t p1 = pack2(fmaxf(acc[mi][ni][2] + bv0, 0.f),
                                        fmaxf(acc[mi][ni][3] + bv1, 0.f));
                    uint32_t cb = (uint32_t)(c * 2);
                    uint32_t a0 = sH + r0 * 512 + (cb ^ ((r0 & 7) << 4));
                    uint32_t a1 = sH + r1 * 512 + (cb ^ ((r1 & 7) << 4));
                    asm volatile("st.shared.b32 [%0], %1;" :: "r"(a0), "r"(p0) : "memory");
                    asm volatile("st.shared.b32 [%0], %1;" :: "r"(a1), "r"(p1) : "memory");
                }
            }
        }
        __syncthreads();
    }

    // ---------- phase 2: x = relu(h1 @ W2 + b2), N=128, K=256 ----------
    loadB(W2h, 256, 0, 0, 0, 128);
    for (int t = 0; t < 8; t++) {
        int cp = t >> 2, kc = t & 3;
        if (t + 1 < 8) {
            loadB(W2h, 256, ((t + 1) >> 2) * 64, ((t + 1) & 3) * 64, (t + 1) & 1, 128);
            asm volatile("cp.async.wait_group 1;" ::: "memory");
        } else {
            asm volatile("cp.async.wait_group 0;" ::: "memory");
        }
        __syncthreads();
        if (kc == 0) zacc();
        uint32_t bBuf = sB + (t & 1) * 8192;
        #pragma unroll
        for (int ks = 0; ks < 4; ks++) {
            uint32_t ah[2][4], bh[4][2];
            #pragma unroll
            for (int mi = 0; mi < 2; mi++) {
                uint32_t row = wm * 32 + mi * 16 + aRowIdx;
                uint32_t cb = (uint32_t)(kc * 128 + ks * 32) + aK16;
                ldsm4(ah[mi], sH + row * 512 + (cb ^ ((row & 7) << 4)));
            }
            #pragma unroll
            for (int pr = 0; pr < 2; pr++) {
                uint32_t row = wn * 32 + pr * 16 + bRowIdx;
                uint32_t cb = (uint32_t)(ks * 32) + bK16;
                uint32_t tr[4];
                ldsm4(tr, bBuf + row * 128 + (cb ^ ((row & 7) << 4)));
                bh[pr*2][0] = tr[0]; bh[pr*2][1] = tr[1];
                bh[pr*2+1][0] = tr[2]; bh[pr*2+1][1] = tr[3];
            }
            #pragma unroll
            for (int mi = 0; mi < 2; mi++)
                #pragma unroll
                for (int ni = 0; ni < 4; ni++)
                    mma16816(acc[mi][ni], ah[mi], bh[ni]);
        }
        if (kc == 3) {
            #pragma unroll
            for (int mi = 0; mi < 2; mi++) {
                int rl0 = wm * 32 + mi * 16 + group;
                int rl1 = rl0 + 8;
                int r0 = rowBase + rl0;
                int r1 = rowBase + rl1;
                #pragma unroll
                for (int ni = 0; ni < 4; ni++) {
                    int c = cp * 64 + wn * 32 + ni * 8 + qc;
                    float bv0 = __ldg(&b2[c]), bv1 = __ldg(&b2[c + 1]);
                    float v00 = fmaxf(acc[mi][ni][0] + bv0, 0.f);
                    float v01 = fmaxf(acc[mi][ni][1] + bv1, 0.f);
                    float v10 = fmaxf(acc[mi][ni][2] + bv0, 0.f);
                    float v11 = fmaxf(acc[mi][ni][3] + bv1, 0.f);
                    uint32_t h0, l0, h1, l1;
                    split2(v00, v01, h0, l0);
                    split2(v10, v11, h1, l1);
                    if (HEAD == 0) {
                        if (r0 < NN) {
                            *(uint32_t*)(Xh + (size_t)r0 * HH + c) = h0;
                            *(uint32_t*)(Xl + (size_t)r0 * HH + c) = l0;
                        }
                        if (r1 < NN) {
                            *(uint32_t*)(Xh + (size_t)r1 * HH + c) = h1;
                            *(uint32_t*)(Xl + (size_t)r1 * HH + c) = l1;
                        }
                    } else {
                        uint32_t cb = (uint32_t)(c * 2);
                        uint32_t a0 = rl0 * 256 + (cb ^ ((rl0 & 7) << 4));
                        uint32_t a1 = rl1 * 256 + (cb ^ ((rl1 & 7) << 4));
                        asm volatile("st.shared.b32 [%0], %1;" :: "r"(sXh + a0), "r"(h0) : "memory");
                        asm volatile("st.shared.b32 [%0], %1;" :: "r"(sXl + a0), "r"(l0) : "memory");
                        asm volatile("st.shared.b32 [%0], %1;" :: "r"(sXh + a1), "r"(h1) : "memory");
                        asm volatile("st.shared.b32 [%0], %1;" :: "r"(sXl + a1), "r"(l1) : "memory");
                    }
                }
            }
        }
        __syncthreads();
    }

    // ---------- phase 3 (HEAD): out = (xh+xl) @ lin_W + lin_b ----------
    if (HEAD == 1) {
        loadB(Wlin, 128, 0, 0, 0, OUTD);
        for (int t = 0; t < 4; t++) {
            int cp = t >> 1, kc = t & 1;
            if (t + 1 < 4) {
                loadB(Wlin, 128, ((t + 1) >> 1) * 64, ((t + 1) & 1) * 64, (t + 1) & 1, OUTD);
                asm volatile("cp.async.wait_group 1;" ::: "memory");
            } else {
                asm volatile("cp.async.wait_group 0;" ::: "memory");
            }
            __syncthreads();
            if (kc == 0) zacc();
            uint32_t bBuf = sB + (t & 1) * 8192;
            #pragma unroll
            for (int ks = 0; ks < 4; ks++) {
                uint32_t ah[2][4], al[2][4], bh[4][2];
                #pragma unroll
                for (int mi = 0; mi < 2; mi++) {
                    uint32_t row = wm * 32 + mi * 16 + aRowIdx;
                    uint32_t cb = (uint32_t)(kc * 128 + ks * 32) + aK16;
                    uint32_t off = row * 256 + (cb ^ ((row & 7) << 4));
                    ldsm4(ah[mi], sXh + off);
                    ldsm4(al[mi], sXl + off);
                }
                #pragma unroll
                for (int pr = 0; pr < 2; pr++) {
                    uint32_t row = wn * 32 + pr * 16 + bRowIdx;
                    uint32_t cb = (uint32_t)(ks * 32) + bK16;
                    uint32_t tr[4];
                    ldsm4(tr, bBuf + row * 128 + (cb ^ ((row & 7) << 4)));
                    bh[pr*2][0] = tr[0]; bh[pr*2][1] = tr[1];
                    bh[pr*2+1][0] = tr[2]; bh[pr*2+1][1] = tr[3];
                }
                #pragma unroll
                for (int mi = 0; mi < 2; mi++)
                    #pragma unroll
                    for (int ni = 0; ni < 4; ni++) {
                        mma16816(acc[mi][ni], ah[mi], bh[ni]);
                        mma16816(acc[mi][ni], al[mi], bh[ni]);
                    }
            }
            if (kc == 1) {
                #pragma unroll
                for (int mi = 0; mi < 2; mi++) {
                    int r0 = rowBase + wm * 32 + mi * 16 + group;
                    int r1 = r0 + 8;
                    #pragma unroll
                    for (int ni = 0; ni < 4; ni++) {
                        int c = cp * 64 + wn * 32 + ni * 8 + qc;
                        if (c >= OUTD) continue;
                        float bv0 = __ldg(&blin[c]), bv1 = __ldg(&blin[c + 1]);
                        if (r0 < NN) {
                            float2 v; v.x = acc[mi][ni][0] + bv0; v.y = acc[mi][ni][1] + bv1;
                            *(float2*)(out + (size_t)r0 * OUTD + c) = v;
                        }
                        if (r1 < NN) {
                            float2 v; v.x = acc[mi][ni][2] + bv0; v.y = acc[mi][ni][3] + bv1;
                            *(float2*)(out + (size_t)r1 * OUTD + c) = v;
                        }
                    }
                }
            }
            __syncthreads();
        }
    }
}

// ---------------------------------------------------------------------------
// MERGED encoder kernel: grid (TILES_M, 4), 3 CTAs/SM.
// ---------------------------------------------------------------------------
__global__ void __launch_bounds__(256, 3)
enc_kernel(const __half* __restrict__ xinh, const __half* __restrict__ segh,
           const __half* __restrict__ wall,
           const float* __restrict__ node_b, const float* __restrict__ edge_b,
           __half* __restrict__ xh, __half* __restrict__ xl,
           __half* __restrict__ eamh, __half* __restrict__ eaml,
           const float* __restrict__ inv, const int* __restrict__ degi) {
    constexpr int STG = 24576;
    extern __shared__ char smem[];
    const uint32_t sb = smem_u32(smem);

    const int task = blockIdx.y >> 1;
    const int colBase = (blockIdx.y & 1) * 64;
    const int KT      = task ? 64 : 128;
    const int CHUNKS  = task ? 1 : 2;
    const __half* Ah  = task ? segh : xinh;
    const __half* Bhi = task ? (wall + 16384) : wall;
    const float* bias = task ? edge_b : node_b;
    __half* Ch = task ? eamh : xh;
    __half* Cl = task ? eaml : xl;

    const int tid  = threadIdx.x;
    const int lane = tid & 31;
    const int wid  = tid >> 5;
    const int wm   = wid & 3;
    const int wn   = wid >> 2;
    const int rowBase = blockIdx.x * 128;

    float acc[2][4][4];
    #pragma unroll
    for (int a = 0; a < 2; a++)
        #pragma unroll
        for (int b = 0; b < 4; b++)
            #pragma unroll
            for (int c = 0; c < 4; c++) acc[a][b][c] = 0.f;

    auto load_slab = [&](int stage, int c) {
        uint32_t base = sb + stage * STG;
        int kb = c * 64;
        #pragma unroll
        for (int i = 0; i < 4; i++) {
            int f = tid + i * 256;
            int row = f >> 3, chn = f & 7;
            uint32_t sw = (uint32_t)(chn * 16) ^ (uint32_t)((row & 7) << 4);
            uint32_t da = base + row * 128 + sw;
            int gr = rowBase + row;
            if (gr < NN) cp16(da, Ah + (size_t)gr * KT + kb + chn * 8);
            else         zero16(da);
        }
        #pragma unroll
        for (int i = 0; i < 2; i++) {
            int f = tid + i * 256;
            int row = f >> 3, chn = f & 7;
            uint32_t sw = (uint32_t)(chn * 16) ^ (uint32_t)((row & 7) << 4);
            uint32_t db = base + 16384 + row * 128 + sw;
            cp16(db, Bhi + (size_t)(colBase + row) * KT + kb + chn * 8);
        }
        asm volatile("cp.async.commit_group;" ::: "memory");
    };

    const uint32_t aRowIdx = (uint32_t)(lane & 15);
    const uint32_t aK16    = (uint32_t)((lane >> 4) << 4);
    const uint32_t bRowIdx = (uint32_t)((lane & 7) + ((lane >> 4) << 3));
    const uint32_t bK16    = (uint32_t)(((lane >> 3) & 1) << 4);

    load_slab(0, 0);

    for (int c = 0; c < CHUNKS; c++) {
        if (c + 1 < CHUNKS) {
            load_slab((c + 1) & 1, c + 1);
            asm volatile("cp.async.wait_group 1;" ::: "memory");
        } else {
            asm volatile("cp.async.wait_group 0;" ::: "memory");
        }
        __syncthreads();

        uint32_t bA = sb + (c & 1) * STG;
        uint32_t bB = bA + 16384;
        #pragma unroll
        for (int ks = 0; ks < 4; ks++) {
            uint32_t ah[2][4], bh[4][2];
            #pragma unroll
            for (int mi = 0; mi < 2; mi++) {
                uint32_t row = wm * 32 + mi * 16 + aRowIdx;
                uint32_t cb = (uint32_t)(ks * 32) + aK16;
                ldsm4(ah[mi], bA + row * 128 + (cb ^ ((row & 7) << 4)));
            }
            #pragma unroll
            for (int pr = 0; pr < 2; pr++) {
                uint32_t row = wn * 32 + pr * 16 + bRowIdx;
                uint32_t cb = (uint32_t)(ks * 32) + bK16;
                uint32_t t[4];
                ldsm4(t, bB + row * 128 + (cb ^ ((row & 7) << 4)));
                bh[pr*2][0] = t[0]; bh[pr*2][1] = t[1];
                bh[pr*2+1][0] = t[2]; bh[pr*2+1][1] = t[3];
            }
            #pragma unroll
            for (int mi = 0; mi < 2; mi++)
                #pragma unroll
                for (int ni = 0; ni < 4; ni++)
                    mma16816(acc[mi][ni], ah[mi], bh[ni]);
        }
        if (c + 1 < CHUNKS) __syncthreads();
    }

    const int group = lane >> 2;
    const int qc    = (lane & 3) * 2;
    #pragma unroll
    for (int mi = 0; mi < 2; mi++) {
        int r0 = rowBase + wm * 32 + mi * 16 + group;
        int r1 = r0 + 8;
        float iv0 = 0.f, m0 = 0.f, iv1 = 0.f, m1 = 0.f;
        if (task == 1) {
            if (r0 < NN) { iv0 = __ldg(&inv[r0]); m0 = (__ldg(&degi[r0]) > 0) ? 1.f : 0.f; }
            if (r1 < NN) { iv1 = __ldg(&inv[r1]); m1 = (__ldg(&degi[r1]) > 0) ? 1.f : 0.f; }
        }
        #pragma unroll
        for (int ni = 0; ni < 4; ni++) {
            int c = colBase + wn * 32 + ni * 8 + qc;
            float b0 = __ldg(&bias[c]), b1 = __ldg(&bias[c + 1]);
            float2 v0, v1;
            if (task == 1) {
                v0.x = acc[mi][ni][0] * iv0 + m0 * b0;
                v0.y = acc[mi][ni][1] * iv0 + m0 * b1;
                v1.x = acc[mi][ni][2] * iv1 + m1 * b0;
                v1.y = acc[mi][ni][3] * iv1 + m1 * b1;
            } else {
                v0.x = acc[mi][ni][0] + b0; v0.y = acc[mi][ni][1] + b1;
                v1.x = acc[mi][ni][2] + b0; v1.y = acc[mi][ni][3] + b1;
            }
            if (r0 < NN) {
                uint32_t h, l; split2(v0.x, v0.y, h, l);
                *(uint32_t*)(Ch + (size_t)r0 * HH + c) = h;
                *(uint32_t*)(Cl + (size_t)r0 * HH + c) = l;
            }
            if (r1 < NN) {
                uint32_t h, l; split2(v1.x, v1.y, h, l);
                *(uint32_t*)(Ch + (size_t)r1 * HH + c) = h;
                *(uint32_t*)(Cl + (size_t)r1 * HH + c) = l;
            }
        }
    }
}

// ---------------------------------------------------------------------------
extern "C" void kernel_launch(void* const* d_in, const int* in_sizes, int n_in,
                              void* d_out, int out_size) {
    const float* x_in   = (const float*)d_in[0];
    const float* eattr  = (const float*)d_in[1];
    const int*   eidx   = (const int*)  d_in[2];
    const float* node_W = (const float*)d_in[3];
    const float* node_b = (const float*)d_in[4];
    const float* edge_W = (const float*)d_in[5];
    const float* edge_b = (const float*)d_in[6];
    const float* W1     = (const float*)d_in[7];
    const float* b1     = (const float*)d_in[8];
    const float* W2     = (const float*)d_in[9];
    const float* b2     = (const float*)d_in[10];
    const float* eps    = (const float*)d_in[11];
    const float* lin_W  = (const float*)d_in[12];
    const float* lin_b  = (const float*)d_in[13];
    float* out = (float*)d_out;

    float *pseg, *pinv;
    int *pdegi, *prowptr, *pcursor, *pbflag, *pcsrc;
    __half *pwh, *pch, *pxh, *pxl, *peamh, *peaml, *pxinh, *psegh;
    cudaGetSymbolAddress((void**)&pseg, g_seg);
    cudaGetSymbolAddress((void**)&pinv, g_inv);
    cudaGetSymbolAddress((void**)&pdegi, g_degi);
    cudaGetSymbolAddress((void**)&prowptr, g_rowptr);
    cudaGetSymbolAddress((void**)&pcursor, g_cursor);
    cudaGetSymbolAddress((void**)&pbflag, g_bflag);
    cudaGetSymbolAddress((void**)&pcsrc, g_csrc);
    cudaGetSymbolAddress((void**)&pwh,  g_whi);
    cudaGetSymbolAddress((void**)&pch,  g_ch);
    cudaGetSymbolAddress((void**)&pxh,  g_xh);
    cudaGetSymbolAddress((void**)&pxl,  g_xl);
    cudaGetSymbolAddress((void**)&peamh, g_eamh);
    cudaGetSymbolAddress((void**)&peaml, g_eaml);
    cudaGetSymbolAddress((void**)&pxinh, g_xinh);
    cudaGetSymbolAddress((void**)&psegh, g_segh);

    constexpr int SM_ENC  = 49152;
    constexpr int SM_MLP0 = 65536;
    constexpr int SM_MLP1 = 98304;
    auto setsm = [](const void* f, int b) {
        cudaFuncSetAttribute(f, cudaFuncAttributeMaxDynamicSharedMemorySize, b);
    };
    setsm((const void*)enc_kernel, SM_ENC);
    setsm((const void*)mlp_fused<0>, SM_MLP0);
    setsm((const void*)mlp_fused<1>, SM_MLP1);

    // ---- resets ----
    cudaMemsetAsync(pdegi, 0, NN * sizeof(int));
    cudaMemsetAsync(pseg, 0, (size_t)NN * IN_EDGE * sizeof(float));
    cudaMemsetAsync(pbflag, 0, NB * sizeof(int));

    // ---- front: weight prep + deg + seg scatter + x_in round ----
    front_kernel<<<FB_W + FB_DEG + FB_SEG + FB_X, 256>>>(
        node_W, edge_W, W1, W2, lin_W, pwh, eidx, pdegi, eattr, pseg, x_in, pxinh);

    // ---- scan, then merged seg2h + csr_fill ----
    scan_fused<<<NB, 256>>>(pdegi, pbflag, prowptr, pcursor, pinv);
    mid_kernel<<<MB_SEG + (EE + 255) / 256, 256>>>(pseg, psegh, eidx, pcursor, pcsrc);

    // ---- merged encoders (node + edge in one launch) ----
    enc_kernel<<<dim3(TILES_M, 4), 256, SM_ENC>>>(pxinh, psegh, pwh,
        node_b, edge_b, pxh, pxl, peamh, peaml, pinv, pdegi);

    for (int l = 0; l < 3; l++) {
        gather_combine<<<(NN * 32 + 255) / 256, 256>>>(prowptr, pcsrc, pxh, pxl,
            peamh, peaml, pinv, eps, l, pch);
        if (l < 2) {
            mlp_fused<0><<<NBM, 128, SM_MLP0>>>(pch,
                pwh + 24576 + l * 32768, b1 + (size_t)l * HH2,
                pwh + 122880 + l * 32768, b2 + (size_t)l * HH,
                pxh, pxl, nullptr, nullptr, nullptr);
        } else {
            mlp_fused<1><<<NBM, 128, SM_MLP1>>>(pch,
                pwh + 24576 + l * 32768, b1 + (size_t)l * HH2,
                pwh + 122880 + l * 32768, b2 + (size_t)l * HH,
                nullptr, nullptr, pwh + 221184, lin_b, out);
        }
    }
}